// round 1
// baseline (speedup 1.0000x reference)
#include <cuda_runtime.h>
#include <cstdint>

// Problem constants (fixed by the reference):
//   R_MAX=32, S_MAX=2, C_Z=128, IN_FEATS=139
//   table rows: d_res: 66, d_tok: 66, ent-combined: 6  -> 138 rows x 128 ch
#define C_Z      128
#define IN_FEATS 139
#define N_RES    66   // 2*(R_MAX+1)
#define N_ENT    6
#define TAB_ROWS 138  // 66 + 66 + 6

// Scratch: fused gather table, built once per launch by a pre-kernel.
__device__ float g_tab[TAB_ROWS * C_Z];

// ---------------------------------------------------------------------------
// Pre-kernel: build transposed + fused table.
//   rows [0,66)   : Wt[r]          (d_res classes)
//   rows [66,132) : Wt[r]          (d_tok classes, feature index == row index)
//   rows [132,137): Wt[132] + Wt[133+k]  (same_ent=1, d_ch=k in [0,4])
//   row  137      : Wt[138]              (same_ent=0 sentinel)
// W layout: [C_Z, IN_FEATS] row-major -> Wt[f][c] = W[c*IN_FEATS + f]
// ---------------------------------------------------------------------------
__global__ void build_tables_kernel(const float* __restrict__ W) {
    int r = blockIdx.x;          // 0..137
    int c = threadIdx.x;         // 0..127
    const float* wc = W + (size_t)c * IN_FEATS;
    float v;
    if (r < 132) {
        v = wc[r];
    } else if (r < 137) {
        v = wc[132] + wc[133 + (r - 132)];
    } else {
        v = wc[138];
    }
    g_tab[r * C_Z + c] = v;
}

// ---------------------------------------------------------------------------
// Main kernel: one block per query row i. 256 threads = 8 warps.
// Each warp handles j = wid, wid+8, ... ; 32 lanes x float4 = 128 channels.
// ---------------------------------------------------------------------------
__global__ __launch_bounds__(256)
void relpos_kernel(const int* __restrict__ asym,
                   const int* __restrict__ resi,
                   const int* __restrict__ ent,
                   const int* __restrict__ sym,
                   const int* __restrict__ tok,
                   float* __restrict__ out,
                   int N) {
    extern __shared__ float s_tab[];   // TAB_ROWS * C_Z floats = 70656 B

    // Coalesced table copy (float4).
    {
        const float4* src = (const float4*)g_tab;
        float4*       dst = (float4*)s_tab;
        const int n4 = TAB_ROWS * (C_Z / 4);           // 4416
        for (int k = threadIdx.x; k < n4; k += blockDim.x) dst[k] = src[k];
    }
    __syncthreads();

    const int i    = blockIdx.x;
    const int lane = threadIdx.x & 31;
    const int wid  = threadIdx.x >> 5;

    const int ai = asym[i];
    const int ri = resi[i];
    const int ei = ent[i];
    const int si = sym[i];
    const int ti = tok[i];

    const float4* t4 = (const float4*)s_tab;           // [TAB_ROWS][32] float4
    float* out_i = out + (size_t)i * N * C_Z;

    #pragma unroll 2
    for (int j = wid; j < N; j += 8) {
        const int aj = __ldg(asym + j);
        const int rj = __ldg(resi + j);
        const int ej = __ldg(ent  + j);
        const int sj = __ldg(sym  + j);
        const int tj = __ldg(tok  + j);

        const bool same_chain = (ai == aj);

        int dres = min(max(ri - rj + 32, 0), 64);
        if (!same_chain) dres = 65;

        int dtok = min(max(ti - tj + 32, 0), 64);
        if (!(same_chain && ri == rj)) dtok = 65;

        int ec;
        if (ei == ej) ec = min(max(si - sj + 2, 0), 4);
        else          ec = 5;

        const float4 a = t4[dres * 32 + lane];
        const float4 b = t4[(N_RES + dtok) * 32 + lane];
        const float4 c = t4[(2 * N_RES + ec) * 32 + lane];

        float4 o;
        o.x = a.x + b.x + c.x;
        o.y = a.y + b.y + c.y;
        o.z = a.z + b.z + c.z;
        o.w = a.w + b.w + c.w;

        // Streaming store: output is 512MB, keep it out of L2's way.
        __stcs((float4*)(out_i + (size_t)j * C_Z) + lane, o);
    }
}

extern "C" void kernel_launch(void* const* d_in, const int* in_sizes, int n_in,
                              void* d_out, int out_size) {
    const float* W    = (const float*)d_in[0];
    const int*   asym = (const int*)d_in[1];
    const int*   resi = (const int*)d_in[2];
    const int*   ent  = (const int*)d_in[3];
    const int*   sym  = (const int*)d_in[4];
    const int*   tok  = (const int*)d_in[5];
    float*       out  = (float*)d_out;

    const int N = in_sizes[1];   // B*N tokens (B=1)

    const int smem = TAB_ROWS * C_Z * (int)sizeof(float);  // 70656 B > 48K -> opt-in
    cudaFuncSetAttribute(relpos_kernel,
                         cudaFuncAttributeMaxDynamicSharedMemorySize, smem);

    build_tables_kernel<<<TAB_ROWS, C_Z>>>(W);
    relpos_kernel<<<N, 256, smem>>>(asym, resi, ent, sym, tok, out, N);
}

// round 2
// speedup vs baseline: 1.2377x; 1.2377x over previous
#include <cuda_runtime.h>
#include <cstdint>

// Problem constants (fixed by the reference):
//   R_MAX=32, S_MAX=2, C_Z=128, IN_FEATS=139
#define C_Z      128
#define IN_FEATS 139

// Table layout (rows of 128 floats):
//   [0,66)    a rows:  Wt[dres]                       (dres in [0,65])
//   [66,132)  b rows:  Wt[66+dtok]                    (dtok in [0,65])
//   [132,138) c rows:  ec<5 ? Wt[132]+Wt[133+ec] : Wt[138]
//   [138,144) bc rows:  b_sent + c_ec      (b_sent = Wt[131])
//   [144,150) abc rows: a_sent + b_sent + c_ec  (a_sent = Wt[65])
#define ROW_A    0
#define ROW_B    66
#define ROW_C    132
#define ROW_BC   138
#define ROW_ABC  144
#define TAB_ROWS 150

#define N_MAX    1024    // token count (B=1, N=1024 for this problem)

__device__ float g_tab[TAB_ROWS * C_Z];

// ---------------------------------------------------------------------------
// Pre-kernel: build fused table. W layout: [C_Z, IN_FEATS] row-major,
// Wt[f][c] = W[c*IN_FEATS + f].
// ---------------------------------------------------------------------------
__global__ void build_tables_kernel(const float* __restrict__ W) {
    int r = blockIdx.x;          // 0..149
    int c = threadIdx.x;         // 0..127
    const float* wc = W + (size_t)c * IN_FEATS;

    float a_sent = wc[65];
    float b_sent = wc[131];

    float v;
    if (r < 132) {
        v = wc[r];                       // a rows and b rows
    } else {
        int k = (r - 132) % 6;           // ec class for c/bc/abc groups
        float ck = (k < 5) ? (wc[132] + wc[133 + k]) : wc[138];
        if (r < 138)      v = ck;                    // c rows
        else if (r < 144) v = b_sent + ck;           // bc rows
        else              v = a_sent + b_sent + ck;  // abc rows
    }
    g_tab[r * C_Z + c] = v;
}

// ---------------------------------------------------------------------------
// Main kernel: one block per query row i; 256 threads = 8 warps.
// Phase 1: compute packed (rows, case) per j once per block into smem.
// Phase 2: warps sweep j; 1-2 (rarely 3) LDS.128 + STG.128 per pair.
// pk encoding: r0 | r1<<9 | r2<<18 | case<<27   (case: 0=1row, 1=2rows, 2=3rows)
// ---------------------------------------------------------------------------
__global__ __launch_bounds__(256)
void relpos_kernel(const int* __restrict__ asym,
                   const int* __restrict__ resi,
                   const int* __restrict__ ent,
                   const int* __restrict__ sym,
                   const int* __restrict__ tok,
                   float* __restrict__ out,
                   int N) {
    extern __shared__ float s_mem[];
    float*    s_tab = s_mem;                                  // TAB_ROWS*128 floats
    unsigned* s_pk  = (unsigned*)(s_mem + TAB_ROWS * C_Z);    // N entries

    // ---- table copy (coalesced float4) ----
    {
        const float4* src = (const float4*)g_tab;
        float4*       dst = (float4*)s_tab;
        const int n4 = TAB_ROWS * (C_Z / 4);                  // 4800
        for (int k = threadIdx.x; k < n4; k += blockDim.x) dst[k] = src[k];
    }

    const int i = blockIdx.x;
    const int ai = asym[i], ri = resi[i], ei = ent[i], si = sym[i], ti = tok[i];

    // ---- phase 1: per-j packed indices (computed once per block) ----
    for (int j = threadIdx.x; j < N; j += blockDim.x) {
        const int aj = __ldg(asym + j);
        const int rj = __ldg(resi + j);
        const int ej = __ldg(ent  + j);
        const int sj = __ldg(sym  + j);
        const int tj = __ldg(tok  + j);

        int ec = (ei == ej) ? min(max(si - sj + 2, 0), 4) : 5;

        unsigned pk;
        if (ai != aj) {
            // case 0: fully fused single row
            pk = (unsigned)(ROW_ABC + ec);
        } else {
            int dres = min(max(ri - rj + 32, 0), 64);
            if (ri != rj) {
                // case 1: a[dres] + bc[ec]
                pk = (unsigned)(ROW_A + dres)
                   | ((unsigned)(ROW_BC + ec) << 9)
                   | (1u << 27);
            } else {
                // case 2: a[dres] + b[dtok] + c[ec]
                int dtok = min(max(ti - tj + 32, 0), 64);
                pk = (unsigned)(ROW_A + dres)
                   | ((unsigned)(ROW_B + dtok) << 9)
                   | ((unsigned)(ROW_C + ec)  << 18)
                   | (2u << 27);
            }
        }
        s_pk[j] = pk;
    }
    __syncthreads();

    // ---- phase 2: emit output rows ----
    const int lane = threadIdx.x & 31;
    const int wid  = threadIdx.x >> 5;
    const float4* t4 = (const float4*)s_tab;                  // [TAB_ROWS][32]
    float* out_i = out + (size_t)i * N * C_Z;

    for (int j = wid; j < N; j += 8) {
        const unsigned pk = s_pk[j];                          // warp-uniform
        const int r0 = pk & 511;
        float4 v = t4[r0 * 32 + lane];

        const unsigned cs = pk >> 27;
        if (cs != 0) {                                        // warp-uniform branch
            const int r1 = (pk >> 9) & 511;
            const float4 b = t4[r1 * 32 + lane];
            v.x += b.x; v.y += b.y; v.z += b.z; v.w += b.w;
            if (cs == 2) {
                const int r2 = (pk >> 18) & 511;
                const float4 c = t4[r2 * 32 + lane];
                v.x += c.x; v.y += c.y; v.z += c.z; v.w += c.w;
            }
        }
        __stcs((float4*)(out_i + (size_t)j * C_Z) + lane, v);
    }
}

extern "C" void kernel_launch(void* const* d_in, const int* in_sizes, int n_in,
                              void* d_out, int out_size) {
    const float* W    = (const float*)d_in[0];
    const int*   asym = (const int*)d_in[1];
    const int*   resi = (const int*)d_in[2];
    const int*   ent  = (const int*)d_in[3];
    const int*   sym  = (const int*)d_in[4];
    const int*   tok  = (const int*)d_in[5];
    float*       out  = (float*)d_out;

    const int N = in_sizes[1];   // 1024

    const int smem = TAB_ROWS * C_Z * (int)sizeof(float) + N * (int)sizeof(unsigned);
    cudaFuncSetAttribute(relpos_kernel,
                         cudaFuncAttributeMaxDynamicSharedMemorySize, smem);

    build_tables_kernel<<<TAB_ROWS, C_Z>>>(W);
    relpos_kernel<<<N, 256, smem>>>(asym, resi, ent, sym, tok, out, N);
}